// round 11
// baseline (speedup 1.0000x reference)
#include <cuda_runtime.h>

#define BIGV 1e10f
#define TT 1024
#define BB 32
#define DD 64
#define NDIAG 2047   // row+col in [0, 2046]

// Diagonal-major cost scratch: g_cost[b][d][row], d = row+col.
static __device__ float g_cost[(size_t)BB * NDIAG * TT];
// Inter-CTA halo (full-size, no ring) + progress counters.
static __device__ float g_halo[BB][3][2048];
static __device__ int   g_prog[BB][3];

// ---------------------------------------------------------------------------
// Kernel A: cost matrix (unchanged from round 1).
// ---------------------------------------------------------------------------
__global__ __launch_bounds__(256) void cost_kernel(const float* __restrict__ x,
                                                   const float* __restrict__ y) {
    const int bz = blockIdx.z;
    const int br = blockIdx.y;
    const int bc = blockIdx.x;
    const int tid = threadIdx.x;

    __shared__ float arena[2 * 64 * 65];
    __shared__ float x2s[64], y2s[64];
    float* xsT = arena;
    float* ysT = arena + 64 * 65;
    float (*res)[72] = (float (*)[72])arena;

    const float* xb = x + ((size_t)bz * TT + br * 64) * DD;
    const float* yb = y + ((size_t)bz * TT + bc * 64) * DD;

    #pragma unroll
    for (int i = 0; i < 16; i++) {
        int idx = tid + i * 256;
        int r = idx >> 6;
        int d = idx & 63;
        xsT[d * 65 + r] = xb[r * DD + d];
        ysT[d * 65 + r] = yb[r * DD + d];
    }
    __syncthreads();

    if (tid < 64) {
        float s = 0.f;
        #pragma unroll
        for (int k = 0; k < 64; k++) { float v = xsT[k * 65 + tid]; s = fmaf(v, v, s); }
        x2s[tid] = s;
    } else if (tid < 128) {
        int c = tid - 64;
        float s = 0.f;
        #pragma unroll
        for (int k = 0; k < 64; k++) { float v = ysT[k * 65 + c]; s = fmaf(v, v, s); }
        y2s[c] = s;
    }

    const int tx = tid & 15;
    const int ty = tid >> 4;
    float acc[4][4] = {};
    #pragma unroll
    for (int k = 0; k < 64; k++) {
        float xr[4], yc[4];
        #pragma unroll
        for (int r = 0; r < 4; r++) xr[r] = xsT[k * 65 + ty * 4 + r];
        #pragma unroll
        for (int c = 0; c < 4; c++) yc[c] = ysT[k * 65 + tx * 4 + c];
        #pragma unroll
        for (int r = 0; r < 4; r++)
            #pragma unroll
            for (int c = 0; c < 4; c++)
                acc[r][c] = fmaf(xr[r], yc[c], acc[r][c]);
    }
    __syncthreads();

    float xr2[4], yc2[4];
    #pragma unroll
    for (int r = 0; r < 4; r++) xr2[r] = x2s[ty * 4 + r];
    #pragma unroll
    for (int c = 0; c < 4; c++) yc2[c] = y2s[tx * 4 + c];
    #pragma unroll
    for (int r = 0; r < 4; r++)
        #pragma unroll
        for (int c = 0; c < 4; c++)
            res[ty * 4 + r][tx * 4 + c] =
                fmaxf(xr2[r] + yc2[c] - 2.0f * acc[r][c], 0.0f);
    __syncthreads();

    const int wid = tid >> 5, lane = tid & 31;
    const int dbase = br * 64 + bc * 64;
    for (int dl = wid; dl < 127; dl += 8) {
        int rlo = dl > 63 ? dl - 63 : 0;
        int rhi = dl < 63 ? dl : 63;
        size_t gbase = ((size_t)bz * NDIAG + (dbase + dl)) * TT + (size_t)br * 64;
        for (int r0 = rlo; r0 <= rhi; r0 += 32) {
            int r = r0 + lane;
            if (r <= rhi) g_cost[gbase + r] = res[r][dl - r];
        }
    }
}

__global__ void init_kernel() {
    int i = threadIdx.x;
    if (i < BB * 3) ((int*)g_prog)[i] = 0;
}

__device__ __forceinline__ float softmin3(float a, float bb, float c) {
    float mnab = fminf(a, bb);
    float mxab = fmaxf(a, bb);
    float mn   = fminf(mnab, c);
    float hi   = fmaxf(mxab, c);
    float mid  = fmaxf(mnab, fminf(mxab, c));
    float sum  = 1.0f + __expf(mn - mid) + __expf(mn - hi);
    return mn - __logf(sum);
}

// ---------------------------------------------------------------------------
// Kernel B: multi-CTA elastic pipelined DP. 128 CTAs (4 per batch), 128
// threads each (4 warps, 2 rows/thread) -> 4x more SMs than round 10.
// Intra-CTA boundaries: full-size smem halo (no ring), per-warp smem progress
// counters, gate-only elastic sync. Inter-CTA boundaries: full-size gmem halo
// + gmem counters (threadfence release / volatile-poll acquire, counter value
// cached so steady-state polls amortize). Segment specialization from round 9.
// 128 CTAs <= 148 SMs: single wave, spin-wait safe.
// ---------------------------------------------------------------------------
#define SEG 8
#define NSEG 256   // SEG*NSEG = 2048 >= 2047 diagonals (k = 2..2049 last pad)

__global__ __launch_bounds__(128) void dp_kernel(float* __restrict__ out) {
    const int cta = blockIdx.x;       // 0..127
    const int b = cta >> 2;           // batch
    const int q = cta & 3;            // quarter (row band of 256)
    const int t = threadIdx.x;        // 0..127
    const int lane = t & 31;
    const int w = t >> 5;             // warp 0..3 within CTA
    const int W = q * 4 + w;          // global 64-row band 0..15
    const int r0 = W * 64 + lane * 2; // owned rows r0, r0+1

    __shared__ float halo_s[3][2048]; // full-size: producer never blocks
    __shared__ int prog_s[4];

    if (t < 4) prog_s[t] = 0;
    __syncthreads();
    volatile int* vprog = prog_s;

    const bool gm_consume = (w == 0) && (q > 0);
    const bool gm_produce = (w == 3) && (q < 3);

    float v1[2] = {BIGV, BIGV};
    float v2[2] = {BIGV, BIGV};
    float L1 = BIGV;
    float L2 = (W == 0 && lane == 0) ? 0.0f : BIGV;   // d0[0] = 0

    const float* costbase = g_cost + (size_t)b * NDIAG * TT + r0;
    const int kminA = r0 + 2;
    const int kmaxA = r0 + 2 + TT;

    // band-level windows (uniform across warp)
    const int W0 = 64 * W + 2;
    const int W1 = 64 * W + 64 + TT;
    const int F0 = 64 * W + 65;
    const int F1 = 64 * W + 1 + TT;
    const int P0 = 64 * W + 64;
    const int P1 = 64 * W + 2 + TT;

    float res = BIGV;
    float2 cbuf[SEG], nbuf[SEG];
    float hb[8];
    #pragma unroll
    for (int j = 0; j < 8; j++) hb[j] = BIGV;
    int cached_prog = 0;

    // preload segment 0 costs (masked)
    #pragma unroll
    for (int j = 0; j < SEG; j++) {
        int k = 2 + j;
        cbuf[j] = make_float2(0.f, 0.f);
        if ((k >= kminA) & (k <= kmaxA))
            cbuf[j] = *(const float2*)(costbase + (size_t)(k - 2) * TT);
    }

    int k0 = 2;
    for (int s = 0; s < NSEG; s++) {
        const bool active = (k0 <= W1) & (k0 + SEG - 1 >= W0);

        // ---- gate (only when this segment reads neighbor halo) ----
        if (active) {
            if (w > 0) {
                if (vprog[w - 1] < s + 1) {
                    while (vprog[w - 1] < s + 1) __nanosleep(32);
                }
                __threadfence_block();
            } else if (gm_consume) {
                if (cached_prog < s + 1) {
                    while ((cached_prog =
                            *(volatile int*)&g_prog[b][q - 1]) < s + 1)
                        __nanosleep(64);
                }
                // load this segment's 8 halo values (L2; first read, no stale L1)
                float4 h0 = __ldcg((const float4*)&g_halo[b][q - 1][k0 - 2]);
                float4 h1 = __ldcg((const float4*)&g_halo[b][q - 1][k0 + 2]);
                hb[0] = h0.x; hb[1] = h0.y; hb[2] = h0.z; hb[3] = h0.w;
                hb[4] = h1.x; hb[5] = h1.y; hb[6] = h1.z; hb[7] = h1.w;
            }
        }

        // ---- prefetch next segment costs ----
        const int k0n = k0 + SEG;
        if ((k0n <= W1) & (k0n + SEG - 1 >= W0) & (s + 1 < NSEG)) {
            const float* p = costbase + (size_t)(k0n - 2) * TT;
            if ((k0n >= P0) & (k0n + SEG - 1 <= P1)) {
                #pragma unroll
                for (int j = 0; j < SEG; j++)
                    nbuf[j] = *(const float2*)(p + (size_t)j * TT);
            } else {
                #pragma unroll
                for (int j = 0; j < SEG; j++) {
                    int k = k0n + j;
                    nbuf[j] = make_float2(0.f, 0.f);
                    if ((k >= kminA) & (k <= kmaxA))
                        nbuf[j] = *(const float2*)(p + (size_t)j * TT);
                }
            }
        }

        // ---- compute current segment ----
        if (!active) {
            // publish BIGV halos for all 8 diagonals
            if (w < 3) {
                if (lane < SEG) halo_s[w][k0 - 2 + lane] = BIGV;
            } else if (gm_produce) {
                if (lane < SEG) g_halo[b][q][k0 - 2 + lane] = BIGV;
            }
        } else if ((k0 >= F0) & (k0 + SEG - 1 <= F1)) {
            // interior fast path
            #pragma unroll
            for (int j = 0; j < SEG; j++) {
                const int k = k0 + j;
                float cur1 = cbuf[j].y + softmin3(v2[0], v1[0], v1[1]);
                float cur0 = cbuf[j].x + softmin3(L2, L1, v1[0]);

                float nb = __shfl_up_sync(0xffffffffu, cur1, 1);
                if (lane == 31) {
                    if (w < 3) halo_s[w][k - 2] = cur1;
                    else if (gm_produce) g_halo[b][q][k - 2] = cur1;
                }
                if (lane == 0)
                    nb = (W == 0) ? BIGV
                                  : (w == 0 ? hb[j] : halo_s[w - 1][k - 2]);
                L2 = L1; L1 = nb;
                v2[0] = v1[0]; v2[1] = v1[1];
                v1[0] = cur0;  v1[1] = cur1;
                res = cur1;
            }
        } else {
            // edge slow path (masked)
            #pragma unroll
            for (int j = 0; j < SEG; j++) {
                const int k = k0 + j;
                const int rlo = k - 1 - TT;
                const int rhi = k - 2;

                float cur0, cur1;
                if ((k >= kminA) & (k <= kmaxA)) {
                    {
                        float sm = softmin3(v2[0], v1[0], v1[1]);
                        int r = r0 + 1;
                        cur1 = ((r >= rlo) & (r <= rhi)) ? cbuf[j].y + sm : BIGV;
                    }
                    {
                        float sm = softmin3(L2, L1, v1[0]);
                        cur0 = ((r0 >= rlo) & (r0 <= rhi)) ? cbuf[j].x + sm : BIGV;
                    }
                    res = cur1;
                } else {
                    cur0 = BIGV; cur1 = BIGV;
                }

                float nb = __shfl_up_sync(0xffffffffu, cur1, 1);
                if (lane == 31) {
                    if (w < 3) halo_s[w][k - 2] = cur1;
                    else if (gm_produce) g_halo[b][q][k - 2] = cur1;
                }
                if (lane == 0)
                    nb = (W == 0) ? BIGV
                                  : (w == 0 ? hb[j] : halo_s[w - 1][k - 2]);
                L2 = L1; L1 = nb;
                v2[0] = v1[0]; v2[1] = v1[1];
                v1[0] = cur0;  v1[1] = cur1;
            }
        }

        // ---- publish progress ----
        if (w < 3) {
            __threadfence_block();
            if (lane == 0) vprog[w] = s + 1;
        } else if (gm_produce) {
            __threadfence();
            if (lane == 0) *(volatile int*)&g_prog[b][q] = s + 1;
        }

        #pragma unroll
        for (int j = 0; j < SEG; j++) cbuf[j] = nbuf[j];
        k0 = k0n;
    }

    // answer: row 1023 -> q=3, warp 3, lane 31, second row (k = 2048)
    if (q == 3 && t == 127) out[b] = res;
}

extern "C" void kernel_launch(void* const* d_in, const int* in_sizes, int n_in,
                              void* d_out, int out_size) {
    const float* x = (const float*)d_in[0];
    const float* y = (const float*)d_in[1];
    float* out = (float*)d_out;

    dim3 gridA(TT / 64, TT / 64, BB);   // (16, 16, 32)
    cost_kernel<<<gridA, 256>>>(x, y);
    init_kernel<<<1, 128>>>();
    dp_kernel<<<BB * 4, 128>>>(out);
}

// round 12
// speedup vs baseline: 1.1127x; 1.1127x over previous
#include <cuda_runtime.h>
#include <cstdint>

#define BIGV 1e10f
#define TT 1024
#define BB 32
#define DD 64
#define NDIAG 2047   // row+col in [0, 2046]

// Diagonal-major cost scratch: g_cost[b][d][row], d = row+col.
static __device__ float g_cost[(size_t)BB * NDIAG * TT];

// ---------------------------------------------------------------------------
// Kernel A: cost matrix (unchanged from round 1; ~174us).
// ---------------------------------------------------------------------------
__global__ __launch_bounds__(256) void cost_kernel(const float* __restrict__ x,
                                                   const float* __restrict__ y) {
    const int bz = blockIdx.z;
    const int br = blockIdx.y;
    const int bc = blockIdx.x;
    const int tid = threadIdx.x;

    __shared__ float arena[2 * 64 * 65];
    __shared__ float x2s[64], y2s[64];
    float* xsT = arena;
    float* ysT = arena + 64 * 65;
    float (*res)[72] = (float (*)[72])arena;

    const float* xb = x + ((size_t)bz * TT + br * 64) * DD;
    const float* yb = y + ((size_t)bz * TT + bc * 64) * DD;

    #pragma unroll
    for (int i = 0; i < 16; i++) {
        int idx = tid + i * 256;
        int r = idx >> 6;
        int d = idx & 63;
        xsT[d * 65 + r] = xb[r * DD + d];
        ysT[d * 65 + r] = yb[r * DD + d];
    }
    __syncthreads();

    if (tid < 64) {
        float s = 0.f;
        #pragma unroll
        for (int k = 0; k < 64; k++) { float v = xsT[k * 65 + tid]; s = fmaf(v, v, s); }
        x2s[tid] = s;
    } else if (tid < 128) {
        int c = tid - 64;
        float s = 0.f;
        #pragma unroll
        for (int k = 0; k < 64; k++) { float v = ysT[k * 65 + c]; s = fmaf(v, v, s); }
        y2s[c] = s;
    }

    const int tx = tid & 15;
    const int ty = tid >> 4;
    float acc[4][4] = {};
    #pragma unroll
    for (int k = 0; k < 64; k++) {
        float xr[4], yc[4];
        #pragma unroll
        for (int r = 0; r < 4; r++) xr[r] = xsT[k * 65 + ty * 4 + r];
        #pragma unroll
        for (int c = 0; c < 4; c++) yc[c] = ysT[k * 65 + tx * 4 + c];
        #pragma unroll
        for (int r = 0; r < 4; r++)
            #pragma unroll
            for (int c = 0; c < 4; c++)
                acc[r][c] = fmaf(xr[r], yc[c], acc[r][c]);
    }
    __syncthreads();

    float xr2[4], yc2[4];
    #pragma unroll
    for (int r = 0; r < 4; r++) xr2[r] = x2s[ty * 4 + r];
    #pragma unroll
    for (int c = 0; c < 4; c++) yc2[c] = y2s[tx * 4 + c];
    #pragma unroll
    for (int r = 0; r < 4; r++)
        #pragma unroll
        for (int c = 0; c < 4; c++)
            res[ty * 4 + r][tx * 4 + c] =
                fmaxf(xr2[r] + yc2[c] - 2.0f * acc[r][c], 0.0f);
    __syncthreads();

    const int wid = tid >> 5, lane = tid & 31;
    const int dbase = br * 64 + bc * 64;
    for (int dl = wid; dl < 127; dl += 8) {
        int rlo = dl > 63 ? dl - 63 : 0;
        int rhi = dl < 63 ? dl : 63;
        size_t gbase = ((size_t)bz * NDIAG + (dbase + dl)) * TT + (size_t)br * 64;
        for (int r0 = rlo; r0 <= rhi; r0 += 32) {
            int r = r0 + lane;
            if (r <= rhi) g_cost[gbase + r] = res[r][dl - r];
        }
    }
}

// ---------------------- cluster / DSMEM helpers ----------------------------
__device__ __forceinline__ uint32_t smem_u32(const void* p) {
    uint32_t a;
    asm("{ .reg .u64 t; cvta.to.shared.u64 t, %1; cvt.u32.u64 %0, t; }"
        : "=r"(a) : "l"(p));
    return a;
}
__device__ __forceinline__ uint32_t mapa_rank(uint32_t a, uint32_t rank) {
    uint32_t r;
    asm("mapa.shared::cluster.u32 %0, %1, %2;" : "=r"(r) : "r"(a), "r"(rank));
    return r;
}
__device__ __forceinline__ void st_remote_f32(uint32_t a, float v) {
    asm volatile("st.shared::cluster.f32 [%0], %1;" :: "r"(a), "f"(v) : "memory");
}
__device__ __forceinline__ void st_remote_rel_u32(uint32_t a, uint32_t v) {
    asm volatile("st.relaxed.cluster.shared::cluster.u32 [%0], %1;"
                 :: "r"(a), "r"(v) : "memory");
}
__device__ __forceinline__ uint32_t ld_acq_cluster_u32(uint32_t a) {
    uint32_t v;
    asm volatile("ld.acquire.cluster.shared::cta.b32 %0, [%1];"
                 : "=r"(v) : "r"(a) : "memory");
    return v;
}
__device__ __forceinline__ void fence_cluster() {
    asm volatile("fence.acq_rel.cluster;" ::: "memory");
}
__device__ __forceinline__ void cluster_sync_all() {
    asm volatile("barrier.cluster.arrive.aligned;" ::: "memory");
    asm volatile("barrier.cluster.wait.aligned;" ::: "memory");
}

__device__ __forceinline__ float softmin3(float a, float bb, float c) {
    float mnab = fminf(a, bb);
    float mxab = fmaxf(a, bb);
    float mn   = fminf(mnab, c);
    float hi   = fmaxf(mxab, c);
    float mid  = fmaxf(mnab, fminf(mxab, c));
    float sum  = 1.0f + __expf(mn - mid) + __expf(mn - hi);
    return mn - __logf(sum);
}

// ---------------------------------------------------------------------------
// Kernel B: multi-CTA elastic pipelined DP with CLUSTER DSMEM handoff.
// 128 CTAs (clusters of 4 = one batch), 128 threads (4 warps, 2 rows/thread).
// Wall = NDIAG x T_diag(slowest stage); this round makes the CTA-boundary
// stages as cheap as interior ones: producer writes halo directly into the
// consumer's smem (st.shared::cluster, fire-and-forget), releases via
// fence.acq_rel.cluster + relaxed remote counter store; consumer polls its
// OWN smem with ld.acquire.cluster (~30 cyc vs ~500 cyc gmem poll in R11).
// No GPU-scope fences anywhere. Full-size incoming halo: never blocks.
// ---------------------------------------------------------------------------
#define SEG 8
#define NSEG 256   // SEG*NSEG = 2048 >= 2047 diagonals

__global__ void __cluster_dims__(4, 1, 1) __launch_bounds__(128)
dp_kernel(float* __restrict__ out) {
    const int cta = blockIdx.x;       // 0..127
    const int b = cta >> 2;           // batch
    const int q = cta & 3;            // quarter (cluster rank)
    const int t = threadIdx.x;        // 0..127
    const int lane = t & 31;
    const int w = t >> 5;             // warp 0..3
    const int W = q * 4 + w;          // global 64-row band 0..15
    const int r0 = W * 64 + lane * 2; // owned rows r0, r0+1

    __shared__ float halo_s[3][2048]; // intra-CTA halos (w=0..2 produce)
    __shared__ float halo_in[2048];   // incoming from left CTA (remote-written)
    __shared__ int   prog_s[4];       // [0..2] intra counters, [3] remote-written

    if (t < 4) prog_s[t] = 0;
    __syncthreads();
    cluster_sync_all();               // peers' counters zeroed before any remote write
    volatile int* vprog = prog_s;

    // remote addresses (only used by w=3 when q<3)
    uint32_t rem_halo = 0, rem_prog = 0;
    if (q < 3) {
        rem_halo = mapa_rank(smem_u32(halo_in), (uint32_t)(q + 1));
        rem_prog = mapa_rank(smem_u32(&prog_s[3]), (uint32_t)(q + 1));
    }
    const uint32_t loc_prog_in = smem_u32(&prog_s[3]);

    float v1[2] = {BIGV, BIGV};
    float v2[2] = {BIGV, BIGV};
    float L1 = BIGV;
    float L2 = (W == 0 && lane == 0) ? 0.0f : BIGV;   // d0[0] = 0

    const float* costbase = g_cost + (size_t)b * NDIAG * TT + r0;
    const int kminA = r0 + 2;
    const int kmaxA = r0 + 2 + TT;

    // band-level windows (uniform across warp)
    const int W0 = 64 * W + 2;
    const int W1 = 64 * W + 64 + TT;
    const int F0 = 64 * W + 65;
    const int F1 = 64 * W + 1 + TT;
    const int P0 = 64 * W + 64;
    const int P1 = 64 * W + 2 + TT;

    const bool gm_produce = (w == 3) && (q < 3);

    float res = BIGV;
    float2 cbuf[SEG], nbuf[SEG];
    int cached_prog = 0;

    // preload segment 0 costs (masked)
    #pragma unroll
    for (int j = 0; j < SEG; j++) {
        int k = 2 + j;
        cbuf[j] = make_float2(0.f, 0.f);
        if ((k >= kminA) & (k <= kmaxA))
            cbuf[j] = *(const float2*)(costbase + (size_t)(k - 2) * TT);
    }

    int k0 = 2;
    for (int s = 0; s < NSEG; s++) {
        const bool active = (k0 <= W1) & (k0 + SEG - 1 >= W0);

        // ---- gate ----
        if (active) {
            if (w > 0) {
                if (vprog[w - 1] < s + 1) {
                    while (vprog[w - 1] < s + 1) __nanosleep(32);
                }
                __threadfence_block();
            } else if (q > 0) {
                if (cached_prog < s + 1) {
                    while ((cached_prog = (int)ld_acq_cluster_u32(loc_prog_in))
                           < s + 1)
                        __nanosleep(32);
                }
            }
        }

        // ---- prefetch next segment costs ----
        const int k0n = k0 + SEG;
        if ((k0n <= W1) & (k0n + SEG - 1 >= W0) & (s + 1 < NSEG)) {
            const float* p = costbase + (size_t)(k0n - 2) * TT;
            if ((k0n >= P0) & (k0n + SEG - 1 <= P1)) {
                #pragma unroll
                for (int j = 0; j < SEG; j++)
                    nbuf[j] = *(const float2*)(p + (size_t)j * TT);
            } else {
                #pragma unroll
                for (int j = 0; j < SEG; j++) {
                    int k = k0n + j;
                    nbuf[j] = make_float2(0.f, 0.f);
                    if ((k >= kminA) & (k <= kmaxA))
                        nbuf[j] = *(const float2*)(p + (size_t)j * TT);
                }
            }
        }

        // ---- compute current segment ----
        if (!active) {
            if (w < 3) {
                if (lane < SEG) halo_s[w][k0 - 2 + lane] = BIGV;
            } else if (gm_produce) {
                if (lane < SEG)
                    st_remote_f32(rem_halo + (uint32_t)(k0 - 2 + lane) * 4u, BIGV);
            }
        } else if ((k0 >= F0) & (k0 + SEG - 1 <= F1)) {
            // interior fast path
            #pragma unroll
            for (int j = 0; j < SEG; j++) {
                const int k = k0 + j;
                float cur1 = cbuf[j].y + softmin3(v2[0], v1[0], v1[1]);
                float cur0 = cbuf[j].x + softmin3(L2, L1, v1[0]);

                float nb = __shfl_up_sync(0xffffffffu, cur1, 1);
                if (lane == 31) {
                    if (w < 3) halo_s[w][k - 2] = cur1;
                    else if (gm_produce)
                        st_remote_f32(rem_halo + (uint32_t)(k - 2) * 4u, cur1);
                }
                if (lane == 0)
                    nb = (W == 0) ? BIGV
                                  : (w == 0 ? halo_in[k - 2] : halo_s[w - 1][k - 2]);
                L2 = L1; L1 = nb;
                v2[0] = v1[0]; v2[1] = v1[1];
                v1[0] = cur0;  v1[1] = cur1;
                res = cur1;
            }
        } else {
            // edge slow path (masked)
            #pragma unroll
            for (int j = 0; j < SEG; j++) {
                const int k = k0 + j;
                const int rlo = k - 1 - TT;
                const int rhi = k - 2;

                float cur0, cur1;
                if ((k >= kminA) & (k <= kmaxA)) {
                    {
                        float sm = softmin3(v2[0], v1[0], v1[1]);
                        int r = r0 + 1;
                        cur1 = ((r >= rlo) & (r <= rhi)) ? cbuf[j].y + sm : BIGV;
                    }
                    {
                        float sm = softmin3(L2, L1, v1[0]);
                        cur0 = ((r0 >= rlo) & (r0 <= rhi)) ? cbuf[j].x + sm : BIGV;
                    }
                    res = cur1;
                } else {
                    cur0 = BIGV; cur1 = BIGV;
                }

                float nb = __shfl_up_sync(0xffffffffu, cur1, 1);
                if (lane == 31) {
                    if (w < 3) halo_s[w][k - 2] = cur1;
                    else if (gm_produce)
                        st_remote_f32(rem_halo + (uint32_t)(k - 2) * 4u, cur1);
                }
                if (lane == 0)
                    nb = (W == 0) ? BIGV
                                  : (w == 0 ? halo_in[k - 2] : halo_s[w - 1][k - 2]);
                L2 = L1; L1 = nb;
                v2[0] = v1[0]; v2[1] = v1[1];
                v1[0] = cur0;  v1[1] = cur1;
            }
        }

        // ---- publish progress ----
        if (w < 3) {
            __threadfence_block();
            if (lane == 0) vprog[w] = s + 1;
        } else if (gm_produce) {
            fence_cluster();
            if (lane == 0) st_remote_rel_u32(rem_prog, (uint32_t)(s + 1));
        }

        #pragma unroll
        for (int j = 0; j < SEG; j++) cbuf[j] = nbuf[j];
        k0 = k0n;
    }

    // answer: row 1023 -> q=3, warp 3, lane 31, second row (k = 2048)
    if (q == 3 && t == 127) out[b] = res;
}

extern "C" void kernel_launch(void* const* d_in, const int* in_sizes, int n_in,
                              void* d_out, int out_size) {
    const float* x = (const float*)d_in[0];
    const float* y = (const float*)d_in[1];
    float* out = (float*)d_out;

    dim3 gridA(TT / 64, TT / 64, BB);   // (16, 16, 32)
    cost_kernel<<<gridA, 256>>>(x, y);
    dp_kernel<<<BB * 4, 128>>>(out);
}

// round 13
// speedup vs baseline: 1.8455x; 1.6586x over previous
#include <cuda_runtime.h>
#include <cstdint>

#define BIGV 1e10f
#define TT 1024
#define BB 32
#define DD 64
#define NDIAG 2047   // row+col in [0, 2046]

// Diagonal-major cost scratch: g_cost[b][d][row], d = row+col.
static __device__ float g_cost[(size_t)BB * NDIAG * TT];

// ---------------------------------------------------------------------------
// Kernel A: cost matrix (unchanged; ~174us).
// ---------------------------------------------------------------------------
__global__ __launch_bounds__(256) void cost_kernel(const float* __restrict__ x,
                                                   const float* __restrict__ y) {
    const int bz = blockIdx.z;
    const int br = blockIdx.y;
    const int bc = blockIdx.x;
    const int tid = threadIdx.x;

    __shared__ float arena[2 * 64 * 65];
    __shared__ float x2s[64], y2s[64];
    float* xsT = arena;
    float* ysT = arena + 64 * 65;
    float (*res)[72] = (float (*)[72])arena;

    const float* xb = x + ((size_t)bz * TT + br * 64) * DD;
    const float* yb = y + ((size_t)bz * TT + bc * 64) * DD;

    #pragma unroll
    for (int i = 0; i < 16; i++) {
        int idx = tid + i * 256;
        int r = idx >> 6;
        int d = idx & 63;
        xsT[d * 65 + r] = xb[r * DD + d];
        ysT[d * 65 + r] = yb[r * DD + d];
    }
    __syncthreads();

    if (tid < 64) {
        float s = 0.f;
        #pragma unroll
        for (int k = 0; k < 64; k++) { float v = xsT[k * 65 + tid]; s = fmaf(v, v, s); }
        x2s[tid] = s;
    } else if (tid < 128) {
        int c = tid - 64;
        float s = 0.f;
        #pragma unroll
        for (int k = 0; k < 64; k++) { float v = ysT[k * 65 + c]; s = fmaf(v, v, s); }
        y2s[c] = s;
    }

    const int tx = tid & 15;
    const int ty = tid >> 4;
    float acc[4][4] = {};
    #pragma unroll
    for (int k = 0; k < 64; k++) {
        float xr[4], yc[4];
        #pragma unroll
        for (int r = 0; r < 4; r++) xr[r] = xsT[k * 65 + ty * 4 + r];
        #pragma unroll
        for (int c = 0; c < 4; c++) yc[c] = ysT[k * 65 + tx * 4 + c];
        #pragma unroll
        for (int r = 0; r < 4; r++)
            #pragma unroll
            for (int c = 0; c < 4; c++)
                acc[r][c] = fmaf(xr[r], yc[c], acc[r][c]);
    }
    __syncthreads();

    float xr2[4], yc2[4];
    #pragma unroll
    for (int r = 0; r < 4; r++) xr2[r] = x2s[ty * 4 + r];
    #pragma unroll
    for (int c = 0; c < 4; c++) yc2[c] = y2s[tx * 4 + c];
    #pragma unroll
    for (int r = 0; r < 4; r++)
        #pragma unroll
        for (int c = 0; c < 4; c++)
            res[ty * 4 + r][tx * 4 + c] =
                fmaxf(xr2[r] + yc2[c] - 2.0f * acc[r][c], 0.0f);
    __syncthreads();

    const int wid = tid >> 5, lane = tid & 31;
    const int dbase = br * 64 + bc * 64;
    for (int dl = wid; dl < 127; dl += 8) {
        int rlo = dl > 63 ? dl - 63 : 0;
        int rhi = dl < 63 ? dl : 63;
        size_t gbase = ((size_t)bz * NDIAG + (dbase + dl)) * TT + (size_t)br * 64;
        for (int r0 = rlo; r0 <= rhi; r0 += 32) {
            int r = r0 + lane;
            if (r <= rhi) g_cost[gbase + r] = res[r][dl - r];
        }
    }
}

__device__ __forceinline__ float softmin3(float a, float bb, float c) {
    float mnab = fminf(a, bb);
    float mxab = fmaxf(a, bb);
    float mn   = fminf(mnab, c);
    float hi   = fmaxf(mxab, c);
    float mid  = fmaxf(mnab, fminf(mxab, c));
    float sum  = 1.0f + __expf(mn - mid) + __expf(mn - hi);
    return mn - __logf(sum);
}

// ---------------------------------------------------------------------------
// Kernel B: elastic pipelined DP with a BRANCH-FREE, MEMORY-FREE inner loop.
// 32 CTAs (1/batch), 512 threads (16 warps, 2 rows/thread).
// Per segment (SEG=8 diags):
//  - consumer reads left warp's 8 halo values via 2 broadcast LDS.128 -> hb[8]
//  - producer accumulates its 8 boundary values in regs sh[8], stores via
//    2 STS.128 in the epilogue (single short if, once per segment)
//  - inner loop: 2 softmins + shfl + SEL + rotation. No BSSY/BSYNC, no LDS.
// Full-size per-warp halo arrays (15 x 2048 f32 = 120KB dynamic smem):
// producers never block; gate-only elastic progress counters.
// ---------------------------------------------------------------------------
#define SEG 8
#define NSEG 256   // SEG*NSEG = 2048 >= 2047 diagonals (k = 2..2049)
#define HALO_BYTES (15 * 2048 * 4)

__global__ __launch_bounds__(512) void dp_kernel(float* __restrict__ out) {
    extern __shared__ float halo_sm[];   // [15][2048]
    __shared__ int prog[16];

    const int b = blockIdx.x;
    const int t = threadIdx.x;        // 0..511
    const int lane = t & 31;
    const int w = t >> 5;             // warp 0..15
    const int r0 = t << 1;            // owned rows r0, r0+1

    if (t < 16) prog[t] = 0;
    __syncthreads();
    volatile int* vprog = prog;

    float v1_0 = BIGV, v1_1 = BIGV;   // d_{k-1}[r0+1], d_{k-1}[r0+2]
    float v2_0 = BIGV, v2_1 = BIGV;   // d_{k-2}[...]
    float L1 = BIGV;                  // d_{k-1}[r0]
    float L2 = (t == 0) ? 0.0f : BIGV;

    const float* costbase = g_cost + (size_t)b * NDIAG * TT + r0;
    const int kminA = r0 + 2;
    const int kmaxA = r0 + 2 + TT;

    // warp-level windows (uniform across warp)
    const int W0 = 64 * w + 2;
    const int W1 = 64 * w + 64 + TT;
    const int F0 = 64 * w + 65;
    const int F1 = 64 * w + 1 + TT;
    const int P0 = 64 * w + 64;
    const int P1 = 64 * w + 2 + TT;

    float* myhalo = &halo_sm[w * 2048];          // valid only for w<15
    const float* lhalo = &halo_sm[(w - 1) * 2048]; // valid only for w>0

    float res = BIGV;
    float2 cbuf[SEG], nbuf[SEG];
    float hb[SEG];
    #pragma unroll
    for (int j = 0; j < SEG; j++) hb[j] = BIGV;  // w=0 keeps BIGV (d_k[0] = BIG)

    // preload segment 0 costs (masked)
    #pragma unroll
    for (int j = 0; j < SEG; j++) {
        int k = 2 + j;
        cbuf[j] = make_float2(0.f, 0.f);
        if ((k >= kminA) & (k <= kmaxA))
            cbuf[j] = *(const float2*)(costbase + (size_t)(k - 2) * TT);
    }

    int k0 = 2;
    for (int s = 0; s < NSEG; s++) {
        const bool active = (k0 <= W1) & (k0 + SEG - 1 >= W0);

        // ---- gate + batched halo read (once per segment) ----
        if (active && (w > 0)) {
            if (vprog[w - 1] < s + 1) {
                while (vprog[w - 1] < s + 1) __nanosleep(20);
            }
            __threadfence_block();
            float4 h0 = *(const float4*)&lhalo[k0 - 2];  // broadcast LDS.128
            float4 h1 = *(const float4*)&lhalo[k0 + 2];
            hb[0] = h0.x; hb[1] = h0.y; hb[2] = h0.z; hb[3] = h0.w;
            hb[4] = h1.x; hb[5] = h1.y; hb[6] = h1.z; hb[7] = h1.w;
        }

        // ---- prefetch next segment costs ----
        const int k0n = k0 + SEG;
        if ((k0n <= W1) & (k0n + SEG - 1 >= W0) & (s + 1 < NSEG)) {
            const float* p = costbase + (size_t)(k0n - 2) * TT;
            if ((k0n >= P0) & (k0n + SEG - 1 <= P1)) {
                #pragma unroll
                for (int j = 0; j < SEG; j++)
                    nbuf[j] = *(const float2*)(p + (size_t)j * TT);
            } else {
                #pragma unroll
                for (int j = 0; j < SEG; j++) {
                    int k = k0n + j;
                    nbuf[j] = make_float2(0.f, 0.f);
                    if ((k >= kminA) & (k <= kmaxA))
                        nbuf[j] = *(const float2*)(p + (size_t)j * TT);
                }
            }
        }

        // ---- compute segment (branch-free, memory-free inner loops) ----
        float sh[SEG];
        if (!active) {
            #pragma unroll
            for (int j = 0; j < SEG; j++) sh[j] = BIGV;
        } else if ((k0 >= F0) & (k0 + SEG - 1 <= F1)) {
            // interior fast path
            #pragma unroll
            for (int j = 0; j < SEG; j++) {
                float cur1 = cbuf[j].y + softmin3(v2_0, v1_0, v1_1);
                float cur0 = cbuf[j].x + softmin3(L2, L1, v1_0);
                float nb = __shfl_up_sync(0xffffffffu, cur1, 1);
                nb = (lane == 0) ? hb[j] : nb;     // SEL, no branch
                sh[j] = cur1;
                L2 = L1; L1 = nb;
                v2_0 = v1_0; v2_1 = v1_1;
                v1_0 = cur0; v1_1 = cur1;
                res = cur1;
            }
        } else {
            // edge path (masked with selects; still branch-free per diag)
            #pragma unroll
            for (int j = 0; j < SEG; j++) {
                const int k = k0 + j;
                const int rlo = k - 1 - TT;
                const int rhi = k - 2;
                const bool tv = (k >= kminA) & (k <= kmaxA);

                float sm1 = softmin3(v2_0, v1_0, v1_1);
                float sm0 = softmin3(L2, L1, v1_0);
                int r1 = r0 + 1;
                float cur1 = (tv & (r1 >= rlo) & (r1 <= rhi)) ? cbuf[j].y + sm1 : BIGV;
                float cur0 = (tv & (r0 >= rlo) & (r0 <= rhi)) ? cbuf[j].x + sm0 : BIGV;
                res = tv ? cur1 : res;

                float nb = __shfl_up_sync(0xffffffffu, cur1, 1);
                nb = (lane == 0) ? hb[j] : nb;
                sh[j] = cur1;
                L2 = L1; L1 = nb;
                v2_0 = v1_0; v2_1 = v1_1;
                v1_0 = cur0; v1_1 = cur1;
            }
        }

        // ---- epilogue: batched halo store + progress publish ----
        if (w < 15) {
            if (lane == 31) {
                *(float4*)&myhalo[k0 - 2] = make_float4(sh[0], sh[1], sh[2], sh[3]);
                *(float4*)&myhalo[k0 + 2] = make_float4(sh[4], sh[5], sh[6], sh[7]);
            }
            __threadfence_block();
            if (lane == 0) vprog[w] = s + 1;
        }

        #pragma unroll
        for (int j = 0; j < SEG; j++) cbuf[j] = nbuf[j];
        k0 = k0n;
    }

    // answer = d_{2T}[T]: row 1023 -> thread 511, second row (k = 2048)
    if (t == 511) out[b] = res;
}

extern "C" void kernel_launch(void* const* d_in, const int* in_sizes, int n_in,
                              void* d_out, int out_size) {
    const float* x = (const float*)d_in[0];
    const float* y = (const float*)d_in[1];
    float* out = (float*)d_out;

    cudaFuncSetAttribute(dp_kernel,
                         cudaFuncAttributeMaxDynamicSharedMemorySize, HALO_BYTES);

    dim3 gridA(TT / 64, TT / 64, BB);   // (16, 16, 32)
    cost_kernel<<<gridA, 256>>>(x, y);
    dp_kernel<<<BB, 512, HALO_BYTES>>>(out);
}